// round 15
// baseline (speedup 1.0000x reference)
#include <cuda_runtime.h>
#include <cuda_bf16.h>

#define B_ 512
#define T_ 512
#define N_ 64

#define L2E 1.4426950408889634f   // log2(e)
#define LN2 0.6931471805599453f   // ln(2)

__device__ int d_order[B_];

// Rank batches by length desc (ties by index): d_order[rank] = batch.
__global__ void rank_kernel(const int* __restrict__ lens) {
    __shared__ int sl[B_];
    const int t = threadIdx.x;
    sl[t] = lens[t];
    __syncthreads();
    const int lb = sl[t];
    int r = 0;
#pragma unroll 8
    for (int k = 0; k < B_; k++) {
        const int lk = sl[k];
        r += (lk > lb) || (lk == lb && k < t);
    }
    d_order[r] = t;
}

__device__ __forceinline__ float ex2(float x) {
    float r; asm("ex2.approx.f32 %0, %1;" : "=f"(r) : "f"(x)); return r;
}
__device__ __forceinline__ float lg2(float x) {
    float r; asm("lg2.approx.f32 %0, %1;" : "=f"(r) : "f"(x)); return r;
}
// Exact floor-log2 rescale shift via exponent bit-extract (+6 centering).
__device__ __forceinline__ float expq(float E0) {
    return (float)((int)((__float_as_uint(E0) >> 23) & 0xFF) - 121);
}
__device__ __forceinline__ unsigned int to_tf32(float f) {
    unsigned int u; asm("cvt.rna.tf32.f32 %0, %1;" : "=r"(u) : "f"(f)); return u;
}
// D[16x8] += A[16x8(tf32)] x B[8x8(tf32)]
__device__ __forceinline__ void mma8(float* d, const unsigned int* a,
                                     const unsigned int* b) {
    asm("mma.sync.aligned.m16n8k8.row.col.f32.tf32.tf32.f32 "
        "{%0,%1,%2,%3}, {%4,%5,%6,%7}, {%8,%9}, {%0,%1,%2,%3};"
        : "+f"(d[0]), "+f"(d[1]), "+f"(d[2]), "+f"(d[3])
        : "r"(a[0]), "r"(a[1]), "r"(a[2]), "r"(a[3]), "r"(b[0]), "r"(b[1]));
}

// TENSOR-CORE CRF: 8 same-direction chains per warp via m16n8k8 tf32 MMA.
// 32 blocks x 4 warps; block g: warps 0,1 = fwd/bwd of rank-octet g (long),
// warps 2,3 = fwd/bwd of octet 63-g (short; they also compute all sequence
// scores in their slack). Each warp: M matrix as 32 constant A-fragments in
// registers (128 regs); per step: B-load from SMEM W with per-element emission
// scale (linear-domain recursion, exact power-of-2 rescale q per chain per
// step), 32 HMMA, D -> SMEM. fb-split exact join (rounds 8-14).
__global__ __launch_bounds__(128) void crf_mma(
    const float* __restrict__ inputs,   // [B, T, N]
    const float* __restrict__ trans,    // [N, N]
    const int*   __restrict__ tags,     // [B, T]
    const int*   __restrict__ lens,     // [B]
    float*       __restrict__ out)      // [B + N*N]
{
    const int bid  = blockIdx.x;        // 0..31
    const int tid  = threadIdx.x;
    const int wid  = tid >> 5;
    const int lane = tid & 31;
    const int tg   = lane & 3;          // threadID_in_group
    const int gp   = lane >> 2;         // groupID = my chain (0..7)
    const int oct  = (wid < 2) ? bid : (63 - bid);
    const int dir  = wid & 1;           // 0 = forward, 1 = backward

    // W: raw GEMM state [tag][chain], stride 8 (B-load conflict-free).
    // E: staged emissions [chain][tag], stride 68 (conflict-free, 16B-aligned).
    __shared__ __align__(16) float Wst[4][2][N_ * 8];
    __shared__ __align__(16) float Est[4][8 * 68];
    __shared__ __align__(16) float Fin[4][8 * 68];
    __shared__ float Rsh[4][8];
    __shared__ float scs[2][8];

    // Passthrough copy of transition_params: 32 blocks x 32 float4 = 4096.
    if (tid < 32) {
        const int idx = bid * 32 + tid;
        reinterpret_cast<float4*>(out + B_)[idx] =
            reinterpret_cast<const float4*>(trans)[idx];
    }

    // A fragments: Afr[mt][kt][4], tf32 of exp2(trans2). m16n8k8 layout:
    // a0:(gp, tg) a1:(gp+8, tg) a2:(gp, tg+4) a3:(gp+8, tg+4) within tile.
    // fwd: M[i][j] = exp(trans[j][i]); bwd: M[i][j] = exp(trans[i][j]).
    unsigned int Afr[4][8][4];
#pragma unroll
    for (int mt = 0; mt < 4; mt++)
#pragma unroll
        for (int kt = 0; kt < 8; kt++) {
            const int r0 = 16 * mt + gp, r1 = r0 + 8;
            const int c0 = 8 * kt + tg, c1 = c0 + 4;
            const int i00 = dir ? (r0 * N_ + c0) : (c0 * N_ + r0);
            const int i10 = dir ? (r1 * N_ + c0) : (c0 * N_ + r1);
            const int i01 = dir ? (r0 * N_ + c1) : (c1 * N_ + r0);
            const int i11 = dir ? (r1 * N_ + c1) : (c1 * N_ + r1);
            Afr[mt][kt][0] = to_tf32(ex2(trans[i00] * L2E));
            Afr[mt][kt][1] = to_tf32(ex2(trans[i10] * L2E));
            Afr[mt][kt][2] = to_tf32(ex2(trans[i01] * L2E));
            Afr[mt][kt][3] = to_tf32(ex2(trans[i11] * L2E));
        }

    // My chain (= gp) parameters.
    const int bb = d_order[oct * 8 + gp];
    const float* em = inputs + (size_t)bb * T_ * N_;
    const int len = lens[bb];
    const int L  = (len > 1) ? len - 1 : 0;
    const int fs = L >> 1;
    const int ns = dir ? (L - fs) : fs;      // my GEMM count
    const int ne = dir ? (ns - 1) : ns;      // last k with a real emission
    const int st = dir ? L : 0;
    const int dr = dir ? -1 : 1;

    int nsMax = ns;
#pragma unroll
    for (int o = 16; o; o >>= 1)
        nsMax = max(nsMax, __shfl_xor_sync(0xffffffffu, nsMax, o));

    // Init: W[0] = V_0, E = 0. (bwd with ns==0: V_0 = ones, R = 0.)
    float R;
    {
        const bool ones = (dir && ns == 0);
        const float r0s = ones ? 0.0f : __ldg(&em[(size_t)st * N_]) * L2E;
        R = r0s;
        float* W0 = Wst[wid][0];
#pragma unroll
        for (int j = 0; j < 4; j++) {
            const int tb = 4 * tg + 16 * j;
            float4 ev = make_float4(0.f, 0.f, 0.f, 0.f);
            if (!ones) ev = *reinterpret_cast<const float4*>(&em[(size_t)st * N_ + tb]);
            W0[(tb + 0) * 8 + gp] = ones ? 1.0f : ex2(fmaf(ev.x, L2E, -r0s));
            W0[(tb + 1) * 8 + gp] = ones ? 1.0f : ex2(fmaf(ev.y, L2E, -r0s));
            W0[(tb + 2) * 8 + gp] = ones ? 1.0f : ex2(fmaf(ev.z, L2E, -r0s));
            W0[(tb + 3) * 8 + gp] = ones ? 1.0f : ex2(fmaf(ev.w, L2E, -r0s));
            *reinterpret_cast<float4*>(&Est[wid][gp * 68 + tb]) =
                make_float4(0.f, 0.f, 0.f, 0.f);
        }
    }
    __syncwarp();

    // Main loop. Iteration k: B = m_{k-1} o W_{k-1} (scale: ex2(emit2 - q),
    // q = exact floor-log2 of W_{k-1}[0][chain]); W_k = M x B; stage emission
    // row r_k for next iteration. Chain gp's final V is its scaled B at
    // iteration ns+1 (-> Fin). Frozen chains keep computing harmless garbage.
    int pb = 0;
    for (int k = 1; k <= nsMax; k++) {
        const float* Wprev = Wst[wid][pb];
        float* Wcur = Wst[wid][pb ^ 1];
        const float q = expq(Wprev[gp]);          // W[0][gp]

        float vv[16];
        unsigned int Bf[16];
#pragma unroll
        for (int kt = 0; kt < 8; kt++) {
            const float w0 = Wprev[(8 * kt + tg) * 8 + gp];
            const float w1 = Wprev[(8 * kt + 4 + tg) * 8 + gp];
            const float e0 = Est[wid][gp * 68 + 8 * kt + tg];
            const float e1 = Est[wid][gp * 68 + 8 * kt + 4 + tg];
            const float v0 = ex2(fmaf(e0, L2E, -q)) * w0;
            const float v1 = ex2(fmaf(e1, L2E, -q)) * w1;
            vv[2 * kt] = v0; vv[2 * kt + 1] = v1;
            Bf[2 * kt] = to_tf32(v0); Bf[2 * kt + 1] = to_tf32(v1);
        }
        if (k <= ns + 1) R += q;
        if (__any_sync(0xffffffffu, k == ns + 1)) {
            if (k == ns + 1) {
#pragma unroll
                for (int kt = 0; kt < 8; kt++) {
                    Fin[wid][gp * 68 + 8 * kt + tg]     = vv[2 * kt];
                    Fin[wid][gp * 68 + 8 * kt + 4 + tg] = vv[2 * kt + 1];
                }
            }
        }

        // Prefetch emission row r_k (zeros if out of range) for iteration k+1.
        const bool val = (k <= ne);
        const int row = val ? (st + dr * k) : st;
        float4 pf[4];
#pragma unroll
        for (int j = 0; j < 4; j++) {
            pf[j] = *reinterpret_cast<const float4*>(
                &em[(size_t)row * N_ + 4 * tg + 16 * j]);
            if (!val) pf[j] = make_float4(0.f, 0.f, 0.f, 0.f);
        }

        // Tensor GEMM: D[64x8] = M x B. 32 HMMA, 4-way ILP over m-tiles.
        float D[4][4];
#pragma unroll
        for (int mt = 0; mt < 4; mt++) {
            D[mt][0] = 0.f; D[mt][1] = 0.f; D[mt][2] = 0.f; D[mt][3] = 0.f;
        }
#pragma unroll
        for (int kt = 0; kt < 8; kt++)
#pragma unroll
            for (int mt = 0; mt < 4; mt++)
                mma8(D[mt], Afr[mt][kt], &Bf[2 * kt]);

        // D -> W_cur. D elems: rows (gp, gp+8) per m-tile, cols (2tg, 2tg+1).
#pragma unroll
        for (int mt = 0; mt < 4; mt++) {
            *reinterpret_cast<float2*>(&Wcur[(16 * mt + gp) * 8 + 2 * tg]) =
                make_float2(D[mt][0], D[mt][1]);
            *reinterpret_cast<float2*>(&Wcur[(16 * mt + gp + 8) * 8 + 2 * tg]) =
                make_float2(D[mt][2], D[mt][3]);
        }
        // Stage emissions for next iteration.
#pragma unroll
        for (int j = 0; j < 4; j++)
            *reinterpret_cast<float4*>(&Est[wid][gp * 68 + 4 * tg + 16 * j]) = pf[j];
        __syncwarp();
        pb ^= 1;
    }

    // Epilogue: iteration nsMax+1's load-scale only (Fin for ns == nsMax).
    {
        const int k = nsMax + 1;
        const float* Wprev = Wst[wid][pb];
        const float q = expq(Wprev[gp]);
        if (k <= ns + 1) R += q;
        if (k == ns + 1) {
#pragma unroll
            for (int kt = 0; kt < 8; kt++) {
                const float w0 = Wprev[(8 * kt + tg) * 8 + gp];
                const float w1 = Wprev[(8 * kt + 4 + tg) * 8 + gp];
                const float e0 = Est[wid][gp * 68 + 8 * kt + tg];
                const float e1 = Est[wid][gp * 68 + 8 * kt + 4 + tg];
                Fin[wid][gp * 68 + 8 * kt + tg]     = ex2(fmaf(e0, L2E, -q)) * w0;
                Fin[wid][gp * 68 + 8 * kt + 4 + tg] = ex2(fmaf(e1, L2E, -q)) * w1;
            }
        }
    }
    if (tg == 0) Rsh[wid][gp] = R;

    // Sequence scores: warp 2 -> octet bid, warp 3 -> octet 63-bid (these
    // warps own the short octet's chains, so this work hides in their slack).
    if (wid >= 2) {
        const int srow = wid - 2;
        const int so = srow ? (63 - bid) : bid;
        for (int c = 0; c < 8; c++) {
            const int b = d_order[so * 8 + c];
            const int ln = lens[b];
            const float* emI = inputs + (size_t)b * T_ * N_;
            const int* tgI = tags + b * T_;
            float sc = 0.0f;
            for (int p = lane; p < ln; p += 32)
                sc += emI[p * N_ + tgI[p]];
            for (int p = lane + 1; p < ln; p += 32)
                sc += trans[tgI[p - 1] * N_ + tgI[p]];
#pragma unroll
            for (int o = 16; o; o >>= 1)
                sc += __shfl_xor_sync(0xffffffffu, sc, o);
            if (lane == 0) scs[srow][c] = sc;
        }
    }
    __syncthreads();

    // Joins: warp 0 -> octet bid (warps 0,1), warp 2 -> octet 63-bid (2,3).
    if ((wid & 1) == 0) {
        for (int c = 0; c < 8; c++) {
            const int b = d_order[oct * 8 + c];
            float dv = Fin[wid][c * 68 + lane] * Fin[wid + 1][c * 68 + lane]
                     + Fin[wid][c * 68 + lane + 32] * Fin[wid + 1][c * 68 + lane + 32];
#pragma unroll
            for (int o = 16; o; o >>= 1)
                dv += __shfl_xor_sync(0xffffffffu, dv, o);
            if (lane == 0) {
                const float logZ =
                    (Rsh[wid][c] + Rsh[wid + 1][c] + lg2(dv)) * LN2;
                out[b] = scs[wid >> 1][c] - logZ;
            }
        }
    }
}

extern "C" void kernel_launch(void* const* d_in, const int* in_sizes, int n_in,
                              void* d_out, int out_size) {
    const float* inputs = (const float*)d_in[0];   // [512, 512, 64] f32
    const float* trans  = (const float*)d_in[1];   // [64, 64] f32
    const int*   tags   = (const int*)d_in[2];     // [512, 512] i32
    const int*   lens   = (const int*)d_in[3];     // [512] i32
    float*       out    = (float*)d_out;           // [512 + 4096] f32

    rank_kernel<<<1, B_>>>(lens);
    crf_mma<<<32, 128>>>(inputs, trans, tags, lens, out);
}

// round 16
// speedup vs baseline: 1.3348x; 1.3348x over previous
#include <cuda_runtime.h>
#include <cuda_bf16.h>

#define B_ 512
#define T_ 512
#define N_ 64

#define L2E 1.4426950408889634f   // log2(e)
#define LN2 0.6931471805599453f   // ln(2)

__device__ int d_order[B_];

// Rank batches by length desc (ties by index): d_order[rank] = batch.
__global__ void rank_kernel(const int* __restrict__ lens) {
    __shared__ int sl[B_];
    const int t = threadIdx.x;
    sl[t] = lens[t];
    __syncthreads();
    const int lb = sl[t];
    int r = 0;
#pragma unroll 8
    for (int k = 0; k < B_; k++) {
        const int lk = sl[k];
        r += (lk > lb) || (lk == lb && k < t);
    }
    d_order[r] = t;
}

// ---- packed f32x2 + MUFU helpers (sm_103a) ----
__device__ __forceinline__ void ffma2(unsigned long long &d,
                                      unsigned long long a,
                                      unsigned long long b) {
    asm("fma.rn.f32x2 %0, %1, %2, %0;" : "+l"(d) : "l"(a), "l"(b));
}
__device__ __forceinline__ unsigned long long fadd2(unsigned long long a,
                                                    unsigned long long b) {
    unsigned long long d;
    asm("add.rn.f32x2 %0, %1, %2;" : "=l"(d) : "l"(a), "l"(b));
    return d;
}
__device__ __forceinline__ unsigned long long pack2(float lo, float hi) {
    unsigned long long d;
    asm("mov.b64 %0, {%1, %2};" : "=l"(d) : "f"(lo), "f"(hi));
    return d;
}
__device__ __forceinline__ void unpack2(unsigned long long v, float &lo, float &hi) {
    asm("mov.b64 {%0, %1}, %2;" : "=f"(lo), "=f"(hi) : "l"(v));
}
__device__ __forceinline__ float ex2(float x) {
    float r; asm("ex2.approx.f32 %0, %1;" : "=f"(r) : "f"(x)); return r;
}
__device__ __forceinline__ float lg2(float x) {
    float r; asm("lg2.approx.f32 %0, %1;" : "=f"(r) : "f"(x)); return r;
}
// Exact floor-log2 rescale shift via exponent bit-extract (+6 centering).
__device__ __forceinline__ float expq(float E0) {
    return (float)((int)((__float_as_uint(E0) >> 23) & 0xFF) - 121);
}

// Two-column GEMV: 16 broadcast LDS.128 + 64 FFMA2, 4 accumulators/column.
__device__ __forceinline__ void gemv2(const float* __restrict__ vsrc,
                                      const unsigned long long* __restrict__ ETlo,
                                      const unsigned long long* __restrict__ EThi,
                                      float &sLo, float &sHi) {
    const ulonglong2* ev = reinterpret_cast<const ulonglong2*>(vsrc);
    unsigned long long l0 = 0ull, l1 = 0ull, l2 = 0ull, l3 = 0ull;
    unsigned long long h0 = 0ull, h1 = 0ull, h2 = 0ull, h3 = 0ull;
#pragma unroll
    for (int m = 0; m < 8; m++) {
        const ulonglong2 p = ev[2 * m];
        const ulonglong2 q = ev[2 * m + 1];
        ffma2(l0, p.x, ETlo[4 * m + 0]);
        ffma2(h0, p.x, EThi[4 * m + 0]);
        ffma2(l1, p.y, ETlo[4 * m + 1]);
        ffma2(h1, p.y, EThi[4 * m + 1]);
        ffma2(l2, q.x, ETlo[4 * m + 2]);
        ffma2(h2, q.x, EThi[4 * m + 2]);
        ffma2(l3, q.y, ETlo[4 * m + 3]);
        ffma2(h3, q.y, EThi[4 * m + 3]);
    }
    float a, b;
    unpack2(fadd2(fadd2(l0, l1), fadd2(l2, l3)), a, b);
    sLo = a + b;
    unpack2(fadd2(fadd2(h0, h1), fadd2(h2, h3)), a, b);
    sHi = a + b;
}

// One solo chain: the validated round-9/14 inner loop (unroll-2, exact
// power-of-2 rescale on A-steps, linear-domain recursion, fb-split semantics).
// Final vector lands in V[ns & 1]; returns accumulated log2 shift R.
__device__ __forceinline__ float run_chain(
    const float* __restrict__ em, int len, int dir, int lane,
    const unsigned long long* __restrict__ ETlo,
    const unsigned long long* __restrict__ EThi,
    float (*V)[68], int &nsOut)
{
    const int L  = (len > 1) ? len - 1 : 0;
    const int fs = L >> 1;
    const int ns = dir ? (L - fs) : fs;
    const int ne = dir ? (ns - 1) : ns;    // last k with a real emission
    const int st = dir ? L : 0;
    const int dr = dir ? -1 : 1;
    nsOut = ns;

    float R;
    if (!dir) {
        const float r0 = __ldg(&em[0]) * L2E;
        R = r0;
        V[0][lane]      = ex2(fmaf(em[lane],      L2E, -r0));
        V[0][lane + 32] = ex2(fmaf(em[lane + 32], L2E, -r0));
    } else if (ns > 0) {
        const size_t o = (size_t)st * N_;
        const float r0 = __ldg(&em[o]) * L2E;
        R = r0;
        V[0][lane]      = ex2(fmaf(em[o + lane],      L2E, -r0));
        V[0][lane + 32] = ex2(fmaf(em[o + lane + 32], L2E, -r0));
    } else {
        R = 0.0f;
        V[0][lane] = 1.0f;                 // beta = ones when no bwd steps
        V[0][lane + 32] = 1.0f;
    }

    float eA0 = 0.f, eA1 = 0.f, eB0 = 0.f, eB1 = 0.f;
    if (1 <= ne) { const int r = (st + dr) * N_;     eA0 = em[r + lane]; eA1 = em[r + lane + 32]; }
    if (2 <= ne) { const int r = (st + 2 * dr) * N_; eB0 = em[r + lane]; eB1 = em[r + lane + 32]; }
    __syncwarp();

    int k = 1;
    for (; k + 1 <= ns; k += 2) {
        float nA0 = 0.f, nA1 = 0.f, nB0 = 0.f, nB1 = 0.f;
        if (k + 2 <= ne) { const int r = (st + dr * (k + 2)) * N_; nA0 = em[r + lane]; nA1 = em[r + lane + 32]; }
        if (k + 3 <= ne) { const int r = (st + dr * (k + 3)) * N_; nB0 = em[r + lane]; nB1 = em[r + lane + 32]; }

        // ---- step A (rescaled, exact power-of-2 shift): V[0] -> V[1] ----
        {
            const float q = expq(V[0][0]);
            const float mL = ex2(fmaf(eA0, L2E, -q));
            const float mH = ex2(fmaf(eA1, L2E, -q));
            float sLo, sHi;
            gemv2(&V[0][0], ETlo, EThi, sLo, sHi);
            V[1][lane]      = mL * sLo;
            V[1][lane + 32] = mH * sHi;
            R += q;
            __syncwarp();
        }
        // ---- step B (no rescale): V[1] -> V[0] ----
        {
            const float mL = ex2(eB0 * L2E);
            const float mH = ex2(eB1 * L2E);
            float sLo, sHi;
            gemv2(&V[1][0], ETlo, EThi, sLo, sHi);
            V[0][lane]      = mL * sLo;
            V[0][lane + 32] = mH * sHi;
            __syncwarp();
        }
        eA0 = nA0; eA1 = nA1; eB0 = nB0; eB1 = nB1;
    }
    if (k <= ns) {                         // odd leftover A-type step
        const float q = expq(V[0][0]);
        const float mL = ex2(fmaf(eA0, L2E, -q));
        const float mH = ex2(fmaf(eA1, L2E, -q));
        float sLo, sHi;
        gemv2(&V[0][0], ETlo, EThi, sLo, sHi);
        V[1][lane]      = mL * sLo;
        V[1][lane + 32] = mH * sHi;
        R += q;
        __syncwarp();
    }
    return R;
}

// PHASED SOLO SCHEDULE: 128 blocks x 4 warps. Grid < SM count -> exactly
// 1 block/SM -> 1 warp/SMSP, every chain runs SOLO (the measured-fastest
// per-step config, c1 ~ 416 cyc). Each warp runs TWO chains sequentially:
//   phase 0: batch quad {2*bid, 2*bid+1}        (long,  ns ~ 255 - b)
//   phase 1: batch quad {510-2*bid, 511-2*bid}  (short, ns ~ b)
// so every warp's total is ~255 steps -- perfectly balanced. The register
// matrix depends only on (dir, lane) -> retained across phases. fwd/bwd of
// each batch live in the same block -> intra-block exact join (rounds 8-14).
__global__ __launch_bounds__(128) void crf_solo(
    const float* __restrict__ inputs,   // [B, T, N]
    const float* __restrict__ trans,    // [N, N]
    const int*   __restrict__ tags,     // [B, T]
    const int*   __restrict__ lens,     // [B]
    float*       __restrict__ out)      // [B + N*N]
{
    const int bid  = blockIdx.x;        // 0..127
    const int tid  = threadIdx.x;
    const int wid  = tid >> 5;
    const int lane = tid & 31;
    const int dir  = wid & 1;           // 0 = forward, 1 = backward

    __shared__ __align__(16) float V[4][2][68];     // [warp][buf][vec]
    __shared__ __align__(16) float Fin[2][4][68];   // [phase][warp][vec]
    __shared__ float Rsh[2][4];

    // Passthrough copy of transition_params: 128 blocks x 8 float4 = 4096.
    if (tid < 8) {
        const int idx = bid * 8 + tid;
        reinterpret_cast<float4*>(out + B_)[idx] =
            reinterpret_cast<const float4*>(trans)[idx];
    }

    // Register matrix, packed over contraction index i (shared across phases):
    //  fwd: ET*[m] = exp2(trans[2m..][col]*L2E), cols lane, lane+32
    //  bwd: ET*[m] = exp2(trans[col][2m..]*L2E), rows lane, lane+32
    unsigned long long ETlo[32], EThi[32];
#pragma unroll
    for (int m = 0; m < 32; m++) {
        const int iaL = dir ? (lane * N_ + 2 * m)            : ((2 * m) * N_ + lane);
        const int ibL = dir ? (lane * N_ + 2 * m + 1)        : ((2 * m + 1) * N_ + lane);
        const int iaH = dir ? ((lane + 32) * N_ + 2 * m)     : ((2 * m) * N_ + lane + 32);
        const int ibH = dir ? ((lane + 32) * N_ + 2 * m + 1) : ((2 * m + 1) * N_ + lane + 32);
        ETlo[m] = pack2(ex2(trans[iaL] * L2E), ex2(trans[ibL] * L2E));
        EThi[m] = pack2(ex2(trans[iaH] * L2E), ex2(trans[ibH] * L2E));
    }

#pragma unroll
    for (int phase = 0; phase < 2; phase++) {
        const int qd = phase ? (255 - bid) : bid;            // quad index
        const int b  = d_order[2 * qd + (wid >> 1)];
        int ns;
        const float R = run_chain(inputs + (size_t)b * T_ * N_, lens[b],
                                  dir, lane, ETlo, EThi, V[wid], ns);
        const int par = ns & 1;
        Fin[phase][wid][lane]      = V[wid][par][lane];
        Fin[phase][wid][lane + 32] = V[wid][par][lane + 32];
        if (lane == 0) Rsh[phase][wid] = R;
        __syncwarp();
    }
    __syncthreads();

    // Output: warp w -> batch (phase = w>>1, sel = w&1).
    // That batch's fwd/bwd vectors sit in Fin[phase][2*sel] / [2*sel + 1].
    const int ph = wid >> 1, ps = wid & 1;
    const int b  = d_order[2 * (ph ? (255 - bid) : bid) + ps];
    const int fw = 2 * ps, bw = 2 * ps + 1;

    float dv = Fin[ph][fw][lane]      * Fin[ph][bw][lane]
             + Fin[ph][fw][lane + 32] * Fin[ph][bw][lane + 32];
#pragma unroll
    for (int o = 16; o; o >>= 1)
        dv += __shfl_xor_sync(0xffffffffu, dv, o);

    // Sequence score: unary [0,len) + binary [1,len), strided over 32 lanes.
    const int len = lens[b];
    const float* emI = inputs + (size_t)b * T_ * N_;
    const int* tgI = tags + b * T_;
    float sc = 0.0f;
    for (int p = lane; p < len; p += 32)
        sc += emI[p * N_ + tgI[p]];
    for (int p = lane + 1; p < len; p += 32)
        sc += trans[tgI[p - 1] * N_ + tgI[p]];
#pragma unroll
    for (int o = 16; o; o >>= 1)
        sc += __shfl_xor_sync(0xffffffffu, sc, o);

    if (lane == 0) {
        const float logZ = (Rsh[ph][fw] + Rsh[ph][bw] + lg2(dv)) * LN2;
        out[b] = sc - logZ;
    }
}

extern "C" void kernel_launch(void* const* d_in, const int* in_sizes, int n_in,
                              void* d_out, int out_size) {
    const float* inputs = (const float*)d_in[0];   // [512, 512, 64] f32
    const float* trans  = (const float*)d_in[1];   // [64, 64] f32
    const int*   tags   = (const int*)d_in[2];     // [512, 512] i32
    const int*   lens   = (const int*)d_in[3];     // [512] i32
    float*       out    = (float*)d_out;           // [512 + 4096] f32

    rank_kernel<<<1, B_>>>(lens);
    crf_solo<<<128, 128>>>(inputs, trans, tags, lens, out);
}

// round 17
// speedup vs baseline: 1.7844x; 1.3368x over previous
#include <cuda_runtime.h>
#include <cuda_bf16.h>

#define B_ 512
#define T_ 512
#define N_ 64

#define L2E 1.4426950408889634f   // log2(e)
#define LN2 0.6931471805599453f   // ln(2)

// Length-scheduled warp classes (r14 schedule; solo class binds at 255*c1):
#define R_PAIR 184
#define R_TRI  284
#define R_QUAD 344
#define W_SOLO 368
#define W_PAIR 100
#define W_TRI  40
#define W_QUAD 84
#define NBLK   148        // 148 x 4 = 592 warp slots, exactly 1 per SMSP

__device__ int d_order[B_];

// Rank batches by length desc (ties by index): d_order[rank] = batch.
__global__ void rank_kernel(const int* __restrict__ lens) {
    __shared__ int sl[B_];
    const int t = threadIdx.x;
    sl[t] = lens[t];
    __syncthreads();
    const int lb = sl[t];
    int r = 0;
#pragma unroll 8
    for (int k = 0; k < B_; k++) {
        const int lk = sl[k];
        r += (lk > lb) || (lk == lb && k < t);
    }
    d_order[r] = t;
}

// ---- packed f32x2 + MUFU helpers (sm_103a) ----
__device__ __forceinline__ void ffma2(unsigned long long &d,
                                      unsigned long long a,
                                      unsigned long long b) {
    asm("fma.rn.f32x2 %0, %1, %2, %0;" : "+l"(d) : "l"(a), "l"(b));
}
__device__ __forceinline__ unsigned long long fadd2(unsigned long long a,
                                                    unsigned long long b) {
    unsigned long long d;
    asm("add.rn.f32x2 %0, %1, %2;" : "=l"(d) : "l"(a), "l"(b));
    return d;
}
__device__ __forceinline__ unsigned long long pack2(float lo, float hi) {
    unsigned long long d;
    asm("mov.b64 %0, {%1, %2};" : "=l"(d) : "f"(lo), "f"(hi));
    return d;
}
__device__ __forceinline__ void unpack2(unsigned long long v, float &lo, float &hi) {
    asm("mov.b64 {%0, %1}, %2;" : "=f"(lo), "=f"(hi) : "l"(v));
}
__device__ __forceinline__ float ex2(float x) {
    float r; asm("ex2.approx.f32 %0, %1;" : "=f"(r) : "f"(x)); return r;
}
__device__ __forceinline__ float lg2(float x) {
    float r; asm("lg2.approx.f32 %0, %1;" : "=f"(r) : "f"(x)); return r;
}
// Exact floor-log2 rescale shift via exponent bit-extract (+6 centering).
__device__ __forceinline__ float expq(float E0) {
    return (float)((int)((__float_as_uint(E0) >> 23) & 0xFF) - 121);
}

// Two-column GEMV: 16 broadcast LDS.128 + 64 FFMA2.
__device__ __forceinline__ void gemv2(const float* __restrict__ vsrc,
                                      const unsigned long long* __restrict__ ETlo,
                                      const unsigned long long* __restrict__ EThi,
                                      float &sLo, float &sHi) {
    const ulonglong2* ev = reinterpret_cast<const ulonglong2*>(vsrc);
    unsigned long long l0 = 0ull, l1 = 0ull, l2 = 0ull, l3 = 0ull;
    unsigned long long h0 = 0ull, h1 = 0ull, h2 = 0ull, h3 = 0ull;
#pragma unroll
    for (int m = 0; m < 8; m++) {
        const ulonglong2 p = ev[2 * m];
        const ulonglong2 q = ev[2 * m + 1];
        ffma2(l0, p.x, ETlo[4 * m + 0]);
        ffma2(h0, p.x, EThi[4 * m + 0]);
        ffma2(l1, p.y, ETlo[4 * m + 1]);
        ffma2(h1, p.y, EThi[4 * m + 1]);
        ffma2(l2, q.x, ETlo[4 * m + 2]);
        ffma2(h2, q.x, EThi[4 * m + 2]);
        ffma2(l3, q.y, ETlo[4 * m + 3]);
        ffma2(h3, q.y, EThi[4 * m + 3]);
    }
    float a, b;
    unpack2(fadd2(fadd2(l0, l1), fadd2(l2, l3)), a, b);
    sLo = a + b;
    unpack2(fadd2(fadd2(h0, h1), fadd2(h2, h3)), a, b);
    sHi = a + b;
}

// NCH same-direction chains per warp. Thread owns columns (2*lane, 2*lane+1).
// Rescale shift q for each A-step comes from a lane-0 SHUFFLE of the value
// computed in the previous B-step (identical to the old smem read of V[0][0],
// but issued a step early so its latency hides). First q is exactly 6
// (init normalizes column 0 to 1.0). Unroll-2, exact power-of-2 rescale.
template <int NCH>
__device__ __forceinline__ void run_chains(
    const float* __restrict__ inputs, const int* __restrict__ lens,
    const int* bb, int dir, int lane,
    const unsigned long long* __restrict__ ETlo,
    const unsigned long long* __restrict__ EThi,
    float (*V)[2][68], float* Rout)
{
    const int c0 = 2 * lane;
    const float* em[NCH];
    int ns[NCH], ne[NCH], st[NCH];
    float R[NCH], qn[NCH];
    const int dr = dir ? -1 : 1;

#pragma unroll
    for (int c = 0; c < NCH; c++) {
        em[c] = inputs + (size_t)bb[c] * T_ * N_;
        const int len = lens[bb[c]];
        const int L = (len > 1) ? len - 1 : 0;
        const int fs = L >> 1;
        ns[c] = dir ? (L - fs) : fs;
        ne[c] = dir ? (ns[c] - 1) : ns[c];
        st[c] = dir ? L : 0;
        qn[c] = 6.0f;   // expq(1.0): col 0 is normalized to ~1.0 at init
        if (!dir) {
            const float r0 = __ldg(&em[c][0]) * L2E;
            R[c] = r0;
            const float2 e0 = *reinterpret_cast<const float2*>(&em[c][c0]);
            *reinterpret_cast<float2*>(&V[c][0][c0]) =
                make_float2(ex2(fmaf(e0.x, L2E, -r0)), ex2(fmaf(e0.y, L2E, -r0)));
        } else if (ns[c] > 0) {
            const size_t o = (size_t)st[c] * N_;
            const float r0 = __ldg(&em[c][o]) * L2E;
            R[c] = r0;
            const float2 e0 = *reinterpret_cast<const float2*>(&em[c][o + c0]);
            *reinterpret_cast<float2*>(&V[c][0][c0]) =
                make_float2(ex2(fmaf(e0.x, L2E, -r0)), ex2(fmaf(e0.y, L2E, -r0)));
        } else {
            R[c] = 0.0f;
            *reinterpret_cast<float2*>(&V[c][0][c0]) = make_float2(1.0f, 1.0f);
        }
    }

    float2 eA[NCH], eB[NCH];
#pragma unroll
    for (int c = 0; c < NCH; c++) {
        eA[c] = make_float2(0.f, 0.f); eB[c] = make_float2(0.f, 0.f);
        if (1 <= ne[c]) eA[c] = *reinterpret_cast<const float2*>(&em[c][(st[c] + dr) * N_ + c0]);
        if (2 <= ne[c]) eB[c] = *reinterpret_cast<const float2*>(&em[c][(st[c] + 2 * dr) * N_ + c0]);
    }
    __syncwarp();

    int nsMax = ns[0];
#pragma unroll
    for (int c = 1; c < NCH; c++) nsMax = (ns[c] > nsMax) ? ns[c] : nsMax;

    int k = 1;
    for (; k + 1 <= nsMax; k += 2) {
        float2 nA[NCH], nB[NCH];
#pragma unroll
        for (int c = 0; c < NCH; c++) {
            nA[c] = make_float2(0.f, 0.f); nB[c] = make_float2(0.f, 0.f);
            if (k + 2 <= ne[c]) nA[c] = *reinterpret_cast<const float2*>(&em[c][(st[c] + dr * (k + 2)) * N_ + c0]);
            if (k + 3 <= ne[c]) nB[c] = *reinterpret_cast<const float2*>(&em[c][(st[c] + dr * (k + 3)) * N_ + c0]);
        }
        // ---- step A (rescaled via pre-shuffled q): buf0 -> buf1 ----
        {
            float mL[NCH], mH[NCH], sLo[NCH], sHi[NCH];
#pragma unroll
            for (int c = 0; c < NCH; c++) {
                mL[c] = ex2(fmaf(eA[c].x, L2E, -qn[c]));
                mH[c] = ex2(fmaf(eA[c].y, L2E, -qn[c]));
            }
#pragma unroll
            for (int c = 0; c < NCH; c++) gemv2(&V[c][0][0], ETlo, EThi, sLo[c], sHi[c]);
#pragma unroll
            for (int c = 0; c < NCH; c++) {
                if (k <= ns[c]) {
                    *reinterpret_cast<float2*>(&V[c][1][c0]) =
                        make_float2(mL[c] * sLo[c], mH[c] * sHi[c]);
                    R[c] += qn[c];
                }
            }
            __syncwarp();
        }
        // ---- step B (no rescale): buf1 -> buf0; tail shuffles next q ----
        {
            float mL[NCH], mH[NCH], sLo[NCH], sHi[NCH];
#pragma unroll
            for (int c = 0; c < NCH; c++) {
                mL[c] = ex2(eB[c].x * L2E);
                mH[c] = ex2(eB[c].y * L2E);
            }
#pragma unroll
            for (int c = 0; c < NCH; c++) gemv2(&V[c][1][0], ETlo, EThi, sLo[c], sHi[c]);
#pragma unroll
            for (int c = 0; c < NCH; c++) {
                const float vLo = mL[c] * sLo[c];
                if (k + 1 <= ns[c]) {
                    *reinterpret_cast<float2*>(&V[c][0][c0]) =
                        make_float2(vLo, mH[c] * sHi[c]);
                }
                // Lane 0 owns column 0: broadcast its fresh value for the
                // NEXT A-step's shift (latency hidden under sync + GEMV).
                qn[c] = expq(__shfl_sync(0xffffffffu, vLo, 0));
            }
            __syncwarp();
        }
#pragma unroll
        for (int c = 0; c < NCH; c++) { eA[c] = nA[c]; eB[c] = nB[c]; }
    }
    if (k <= nsMax) {           // odd leftover A-type step
        float mL[NCH], mH[NCH], sLo[NCH], sHi[NCH];
#pragma unroll
        for (int c = 0; c < NCH; c++) {
            mL[c] = ex2(fmaf(eA[c].x, L2E, -qn[c]));
            mH[c] = ex2(fmaf(eA[c].y, L2E, -qn[c]));
        }
#pragma unroll
        for (int c = 0; c < NCH; c++) gemv2(&V[c][0][0], ETlo, EThi, sLo[c], sHi[c]);
#pragma unroll
        for (int c = 0; c < NCH; c++) {
            if (k <= ns[c]) {
                *reinterpret_cast<float2*>(&V[c][1][c0]) =
                    make_float2(mL[c] * sLo[c], mH[c] * sHi[c]);
                R[c] += qn[c];
            }
        }
        __syncwarp();
    }
#pragma unroll
    for (int c = 0; c < NCH; c++) Rout[c] = R[c];
}

__global__ __launch_bounds__(128) void crf_sched(
    const float* __restrict__ inputs,   // [B, T, N]
    const float* __restrict__ trans,    // [N, N]
    const int*   __restrict__ tags,     // [B, T]
    const int*   __restrict__ lens,     // [B]
    float*       __restrict__ out)      // [B + N*N]
{
    const int bid  = blockIdx.x;
    const int tid  = threadIdx.x;
    const int wid  = tid >> 5;
    const int lane = tid & 31;
    const int wg   = bid * 4 + wid;          // global warp slot
    const int c0   = 2 * lane;

    __shared__ __align__(16) float V[4][4][2][68];
    __shared__ float Rsh[4][4];

    // Passthrough copy of transition_params: 128 blocks x 8 float4 = 4096.
    if (bid < 128 && tid < 8) {
        const int idx = bid * 8 + tid;
        reinterpret_cast<float4*>(out + B_)[idx] =
            reinterpret_cast<const float4*>(trans)[idx];
    }

    // Decode class: nch same-direction chains from the sorted order.
    int bb[4] = {0, 0, 0, 0};
    int nch = 0, dir = 0;
    if (wg < W_SOLO) {
        nch = 1; dir = wg & 1;
        bb[0] = d_order[wg >> 1];
    } else if (wg < W_SOLO + W_PAIR) {
        const int i = wg - W_SOLO; dir = i & 1; const int j = i >> 1;
        nch = 2;
        bb[0] = d_order[R_PAIR + 2 * j];
        bb[1] = d_order[R_PAIR + 2 * j + 1];
    } else if (wg < W_SOLO + W_PAIR + W_TRI) {
        const int i = wg - W_SOLO - W_PAIR; dir = i & 1; const int j = i >> 1;
        nch = 3;
        bb[0] = d_order[R_TRI + 3 * j];
        bb[1] = d_order[R_TRI + 3 * j + 1];
        bb[2] = d_order[R_TRI + 3 * j + 2];
    } else {
        const int i = wg - W_SOLO - W_PAIR - W_TRI; dir = i & 1; const int j = i >> 1;
        nch = 4;
        bb[0] = d_order[R_QUAD + 4 * j];
        bb[1] = d_order[R_QUAD + 4 * j + 1];
        bb[2] = d_order[R_QUAD + 4 * j + 2];
        bb[3] = d_order[R_QUAD + 4 * j + 3];
    }

    float Rout[4] = {0.f, 0.f, 0.f, 0.f};
    {
        // Register matrix for my owned columns (2*lane, 2*lane+1):
        //  fwd: ET*[m] = exp2(trans[2m..][col]*L2E)
        //  bwd: ET*[m] = exp2(trans[col][2m..]*L2E)
        unsigned long long ETlo[32], EThi[32];
#pragma unroll
        for (int m = 0; m < 32; m++) {
            const int iaL = dir ? (c0 * N_ + 2 * m)           : ((2 * m) * N_ + c0);
            const int ibL = dir ? (c0 * N_ + 2 * m + 1)       : ((2 * m + 1) * N_ + c0);
            const int iaH = dir ? ((c0 + 1) * N_ + 2 * m)     : ((2 * m) * N_ + c0 + 1);
            const int ibH = dir ? ((c0 + 1) * N_ + 2 * m + 1) : ((2 * m + 1) * N_ + c0 + 1);
            ETlo[m] = pack2(ex2(trans[iaL] * L2E), ex2(trans[ibL] * L2E));
            EThi[m] = pack2(ex2(trans[iaH] * L2E), ex2(trans[ibH] * L2E));
        }
        if (nch == 1)      run_chains<1>(inputs, lens, bb, dir, lane, ETlo, EThi, V[wid], Rout);
        else if (nch == 2) run_chains<2>(inputs, lens, bb, dir, lane, ETlo, EThi, V[wid], Rout);
        else if (nch == 3) run_chains<3>(inputs, lens, bb, dir, lane, ETlo, EThi, V[wid], Rout);
        else               run_chains<4>(inputs, lens, bb, dir, lane, ETlo, EThi, V[wid], Rout);
    }

    if (lane == 0) {
        Rsh[wid][0] = Rout[0]; Rsh[wid][1] = Rout[1];
        Rsh[wid][2] = Rout[2]; Rsh[wid][3] = Rout[3];
    }
    __syncthreads();

    // Join + output: each FWD warp (even wid; partner = wid+1) handles its
    // nch batches: Z = <v_mid, beta_mid>, plus sequence score.
    if (dir == 0) {
        for (int c = 0; c < nch; c++) {
            const int b = bb[c];
            const int len = lens[b];
            const int L = (len > 1) ? len - 1 : 0;
            const int fs = L >> 1;
            const int fpar = fs & 1;
            const int bpar = (L - fs) & 1;

            const float2 vf = *reinterpret_cast<const float2*>(&V[wid][c][fpar][c0]);
            const float2 vb = *reinterpret_cast<const float2*>(&V[wid + 1][c][bpar][c0]);
            float dv = vf.x * vb.x + vf.y * vb.y;
#pragma unroll
            for (int off = 16; off; off >>= 1)
                dv += __shfl_xor_sync(0xffffffffu, dv, off);

            const float* emI = inputs + (size_t)b * T_ * N_;
            const int* tgI = tags + b * T_;
            float sc = 0.0f;
            for (int q = lane; q < len; q += 32)
                sc += emI[q * N_ + tgI[q]];
            for (int q = lane + 1; q < len; q += 32)
                sc += trans[tgI[q - 1] * N_ + tgI[q]];
#pragma unroll
            for (int off = 16; off; off >>= 1)
                sc += __shfl_xor_sync(0xffffffffu, sc, off);

            if (lane == 0) {
                const float logZ = (Rout[c] + Rsh[wid + 1][c] + lg2(dv)) * LN2;
                out[b] = sc - logZ;
            }
        }
    }
}

extern "C" void kernel_launch(void* const* d_in, const int* in_sizes, int n_in,
                              void* d_out, int out_size) {
    const float* inputs = (const float*)d_in[0];   // [512, 512, 64] f32
    const float* trans  = (const float*)d_in[1];   // [64, 64] f32
    const int*   tags   = (const int*)d_in[2];     // [512, 512] i32
    const int*   lens   = (const int*)d_in[3];     // [512] i32
    float*       out    = (float*)d_out;           // [512 + 4096] f32

    rank_kernel<<<1, B_>>>(lens);
    crf_sched<<<NBLK, 128>>>(inputs, trans, tags, lens, out);
}